// round 4
// baseline (speedup 1.0000x reference)
#include <cuda_runtime.h>
#include <cuda_bf16.h>
#include <cstdint>

// ============================ helpers ============================
__device__ __forceinline__ float to_tf32(float x) {
    uint32_t u;
    asm("cvt.rna.tf32.f32 %0, %1;" : "=r"(u) : "f"(x));
    return __uint_as_float(u);
}
__device__ __forceinline__ uint16_t bf16bits(float x) {
    return __bfloat16_as_ushort(__float2bfloat16(x));
}
__device__ __forceinline__ uint32_t packbf(float lo, float hi) {
    return (uint32_t)bf16bits(lo) | ((uint32_t)bf16bits(hi) << 16);
}
__device__ __forceinline__ void mma8(float* c, const uint32_t* a, const uint32_t* b) {
    asm volatile(
        "mma.sync.aligned.m16n8k8.row.col.f32.tf32.tf32.f32 "
        "{%0,%1,%2,%3}, {%4,%5,%6,%7}, {%8,%9}, {%0,%1,%2,%3};"
        : "+f"(c[0]), "+f"(c[1]), "+f"(c[2]), "+f"(c[3])
        : "r"(a[0]), "r"(a[1]), "r"(a[2]), "r"(a[3]), "r"(b[0]), "r"(b[1]));
}
__device__ __forceinline__ void mma16bf(float* c, const uint32_t* a, const uint32_t* b) {
    asm volatile(
        "mma.sync.aligned.m16n8k16.row.col.f32.bf16.bf16.f32 "
        "{%0,%1,%2,%3}, {%4,%5,%6,%7}, {%8,%9}, {%0,%1,%2,%3};"
        : "+f"(c[0]), "+f"(c[1]), "+f"(c[2]), "+f"(c[3])
        : "r"(a[0]), "r"(a[1]), "r"(a[2]), "r"(a[3]), "r"(b[0]), "r"(b[1]));
}

// ============================ device globals ============================
__device__ float g_qh[8388608];                    // query hi (tf32)
__device__ uint16_t g_qbh[8388608], g_qbl[8388608];
__device__ float g_kh[8388608];
__device__ uint16_t g_kbh[8388608], g_kbl[8388608];
__device__ float g_qwh[1048576];
__device__ uint16_t g_qwbh[1048576], g_qwbl[1048576];
__device__ float g_kwh[1048576];
__device__ uint16_t g_kwbh[1048576], g_kwbl[1048576];
__device__ float g_wqh[8388608];                   // projected Q hi [b,h,i,s]
__device__ uint16_t g_wqbh[8388608], g_wqbl[8388608];
__device__ float g_wkh[8388608];
__device__ uint16_t g_wkbh[8388608], g_wkbl[8388608];
__device__ float g_wv[8388608];                    // projected V [b,h,j,s]
__device__ float g_scores[134217728];              // [b,h,i,j]
__device__ float g_heads[8388608];                 // [b,h,i,s]

// ============================ split3: x -> tf32 hi + bf16(hi) + bf16(residual) ============================
__global__ void split3(const float* __restrict__ x, float* __restrict__ hi,
                       uint16_t* __restrict__ bh, uint16_t* __restrict__ bl) {
    size_t i = ((size_t)blockIdx.x * 256 + threadIdx.x) * 8;
    float4 v0 = *(const float4*)(x + i);
    float4 v1 = *(const float4*)(x + i + 4);
    float h[8] = {to_tf32(v0.x), to_tf32(v0.y), to_tf32(v0.z), to_tf32(v0.w),
                  to_tf32(v1.x), to_tf32(v1.y), to_tf32(v1.z), to_tf32(v1.w)};
    float xr[8] = {v0.x, v0.y, v0.z, v0.w, v1.x, v1.y, v1.z, v1.w};
    *(float4*)(hi + i) = make_float4(h[0], h[1], h[2], h[3]);
    *(float4*)(hi + i + 4) = make_float4(h[4], h[5], h[6], h[7]);
    uint4 ph, pl;
    ph.x = packbf(h[0], h[1]); ph.y = packbf(h[2], h[3]);
    ph.z = packbf(h[4], h[5]); ph.w = packbf(h[6], h[7]);
    pl.x = packbf(xr[0] - h[0], xr[1] - h[1]); pl.y = packbf(xr[2] - h[2], xr[3] - h[3]);
    pl.z = packbf(xr[4] - h[4], xr[5] - h[5]); pl.w = packbf(xr[6] - h[6], xr[7] - h[7]);
    *(uint4*)(bh + i) = ph;
    *(uint4*)(bl + i) = pl;
}

// ============================ mixed tf32/bf16 mma GEMM ============================
// C[128 x NTILE] = A[128 x KTOT] * op(B), per blockIdx.z slice.
// SPLIT: D = Ah*Bh (tf32) + bf(Ah)*bf(loB) + bf(loA)*bf(Bh)  (bf16 corrections)
// BMODE: 0 = B row-major [K x N]; 1 = per-head weight [h][k][s]; 2 = B row-major [N x K]
// CMODE: 0 = plain row-major C (+z*cZ), scaled
//        1 = [b,h,i,s] layout: write tf32 hi (f32) + bf16(hi) + bf16(residual)
//        2 = [b,h,i,s] layout: plain f32, scaled
template <int KTOT, int NTILE, bool SPLIT, int BMODE, int CMODE, bool RNDA, bool RNDB,
          int LDA, int LDB, int LDC>
__global__ void __launch_bounds__(256) mma_gemm(
    const float* __restrict__ Ah, const uint16_t* __restrict__ Abh,
    const uint16_t* __restrict__ Abl,
    const float* __restrict__ Bh, const uint16_t* __restrict__ Bbh,
    const uint16_t* __restrict__ Bbl,
    float* __restrict__ Ch, uint16_t* __restrict__ Cbh, uint16_t* __restrict__ Cbl,
    size_t aZ, size_t bZ, size_t cZ, float scale) {
    extern __shared__ float smf[];
    constexpr int LP = 132;
    constexpr int BUF = 16 * LP;     // f32 slab (floats)
    constexpr int BUFB = 8 * LP;     // bf16 slab (u32 words, 2 k per word)
    float* AsH = smf;                // [2][BUF]
    float* BsH = smf + 2 * BUF;      // [2][BUF]
    uint32_t* AbfH = (uint32_t*)(smf + 4 * BUF);  // [2][BUFB]
    uint32_t* AbfL = AbfH + 2 * BUFB;
    uint32_t* BbfH = AbfL + 2 * BUFB;
    uint32_t* BbfL = BbfH + 2 * BUFB;

    const int t = threadIdx.x;
    const int lane = t & 31, wid = t >> 5;
    const int g = lane >> 2, tg = lane & 3;
    constexpr int WARP_M = (NTILE == 128) ? 2 : 4;
    constexpr int WARP_N = 8 / WARP_M;
    constexpr int MT = 128 / (WARP_M * 16);
    constexpr int NT = NTILE / (WARP_N * 8);
    const int wm = (WARP_N == 4) ? (wid >> 2) : (wid >> 1);
    const int wn = (WARP_N == 4) ? (wid & 3) : (wid & 1);

    const int m0 = blockIdx.y * 128;
    const int n0 = blockIdx.x * NTILE;
    const size_t z = blockIdx.z;
    const float* pAh = Ah + z * aZ;
    const float* pBh = Bh + z * bZ;
    const uint16_t* pAbh = SPLIT ? Abh + z * aZ : nullptr;
    const uint16_t* pAbl = SPLIT ? Abl + z * aZ : nullptr;
    const uint16_t* pBbh = SPLIT ? Bbh + z * bZ : nullptr;
    const uint16_t* pBbl = SPLIT ? Bbl + z * bZ : nullptr;

    const int am = t >> 2, ak = (t & 3) << 2;
    const int bk = (NTILE == 128) ? (t >> 5) : (t >> 4);
    const int bn = (NTILE == 128) ? ((t & 31) << 2) : ((t & 15) << 2);
    const int mA = t & 127, khA = t >> 7;  // bf16 A/B(mode2) staging
    const int nB = t & 127, kqB = t >> 7;  // bf16 B(mode1) staging

    float acc[MT][NT][4];
#pragma unroll
    for (int i = 0; i < MT; i++)
#pragma unroll
        for (int j = 0; j < NT; j++)
#pragma unroll
            for (int q = 0; q < 4; q++) acc[i][j][q] = 0.f;

    float4 vah[2], vbh[2];
    uint4 vabh, vabl, vbbh, vbbl;
    uint32_t wbh[4], wbl[4];

    auto cvt4 = [](float4& v) {
        v.x = to_tf32(v.x); v.y = to_tf32(v.y);
        v.z = to_tf32(v.z); v.w = to_tf32(v.w);
    };

    auto loadA = [&](int k0) {
        vah[0] = *(const float4*)(pAh + (size_t)(m0 + am) * LDA + k0 + ak);
        vah[1] = *(const float4*)(pAh + (size_t)(m0 + am + 64) * LDA + k0 + ak);
        if (RNDA) { cvt4(vah[0]); cvt4(vah[1]); }
        if constexpr (SPLIT) {
            vabh = *(const uint4*)(pAbh + (size_t)(m0 + mA) * LDA + k0 + khA * 8);
            vabl = *(const uint4*)(pAbl + (size_t)(m0 + mA) * LDA + k0 + khA * 8);
        }
    };
    auto loadB = [&](int k0) {
        if constexpr (BMODE == 2) {
            vbh[0] = *(const float4*)(pBh + (size_t)(n0 + am) * LDB + k0 + ak);
            vbh[1] = *(const float4*)(pBh + (size_t)(n0 + am + 64) * LDB + k0 + ak);
            if (RNDB) { cvt4(vbh[0]); cvt4(vbh[1]); }
            if constexpr (SPLIT) {
                vbbh = *(const uint4*)(pBbh + (size_t)(n0 + mA) * LDB + k0 + khA * 8);
                vbbl = *(const uint4*)(pBbl + (size_t)(n0 + mA) * LDB + k0 + khA * 8);
            }
        } else if constexpr (BMODE == 1) {
            const int n = n0 + bn;
            const size_t base = ((size_t)(n >> 6) << 16) + (size_t)(n & 63);
            vbh[0] = *(const float4*)(pBh + base + (size_t)(k0 + bk) * 64);
            vbh[1] = *(const float4*)(pBh + base + (size_t)(k0 + bk + 8) * 64);
            if (RNDB) { cvt4(vbh[0]); cvt4(vbh[1]); }
            if constexpr (SPLIT) {
                const int n2 = n0 + nB;
                const size_t b2 = ((size_t)(n2 >> 6) << 16) + (size_t)(n2 & 63);
#pragma unroll
                for (int q = 0; q < 4; q++) {
                    const int k = k0 + (kqB * 4 + q) * 2;
                    wbh[q] = (uint32_t)pBbh[b2 + (size_t)k * 64] |
                             ((uint32_t)pBbh[b2 + (size_t)(k + 1) * 64] << 16);
                    wbl[q] = (uint32_t)pBbl[b2 + (size_t)k * 64] |
                             ((uint32_t)pBbl[b2 + (size_t)(k + 1) * 64] << 16);
                }
            }
        } else {
            vbh[0] = *(const float4*)(pBh + (size_t)(k0 + bk) * LDB + n0 + bn);
            if (NTILE == 128)
                vbh[1] = *(const float4*)(pBh + (size_t)(k0 + bk + 8) * LDB + n0 + bn);
            if (RNDB) { cvt4(vbh[0]); if (NTILE == 128) cvt4(vbh[1]); }
        }
    };
    auto stT = [&](float* dst, const float4* v) {
        dst[(ak + 0) * LP + am] = v[0].x;
        dst[(ak + 1) * LP + am] = v[0].y;
        dst[(ak + 2) * LP + am] = v[0].z;
        dst[(ak + 3) * LP + am] = v[0].w;
        dst[(ak + 0) * LP + am + 64] = v[1].x;
        dst[(ak + 1) * LP + am + 64] = v[1].y;
        dst[(ak + 2) * LP + am + 64] = v[1].z;
        dst[(ak + 3) * LP + am + 64] = v[1].w;
    };
    auto stBF = [&](uint32_t* dst, uint4 v, int mm, int kh) {
        dst[(kh * 4 + 0) * LP + mm] = v.x;
        dst[(kh * 4 + 1) * LP + mm] = v.y;
        dst[(kh * 4 + 2) * LP + mm] = v.z;
        dst[(kh * 4 + 3) * LP + mm] = v.w;
    };
    auto stageAll = [&](int buf) {
        stT(AsH + buf * BUF, vah);
        if constexpr (SPLIT) {
            stBF(AbfH + buf * BUFB, vabh, mA, khA);
            stBF(AbfL + buf * BUFB, vabl, mA, khA);
        }
        if constexpr (BMODE == 2) {
            stT(BsH + buf * BUF, vbh);
            if constexpr (SPLIT) {
                stBF(BbfH + buf * BUFB, vbbh, mA, khA);
                stBF(BbfL + buf * BUFB, vbbl, mA, khA);
            }
        } else {
            float* d = BsH + buf * BUF;
            *(float4*)(d + bk * LP + bn) = vbh[0];
            if (NTILE == 128) *(float4*)(d + (bk + 8) * LP + bn) = vbh[1];
            if constexpr (SPLIT && BMODE == 1) {
                uint32_t* dh = BbfH + buf * BUFB;
                uint32_t* dl = BbfL + buf * BUFB;
#pragma unroll
                for (int q = 0; q < 4; q++) {
                    dh[(kqB * 4 + q) * LP + nB] = wbh[q];
                    dl[(kqB * 4 + q) * LP + nB] = wbl[q];
                }
            }
        }
    };

    auto comboT = [&](const float* Ab, const float* Bb, int kb) {
        uint32_t af[MT][4], bf[NT][2];
#pragma unroll
        for (int mt = 0; mt < MT; mt++) {
            const int m = wm * MT * 16 + mt * 16 + g;
            af[mt][0] = __float_as_uint(Ab[(kb + tg) * LP + m]);
            af[mt][1] = __float_as_uint(Ab[(kb + tg) * LP + m + 8]);
            af[mt][2] = __float_as_uint(Ab[(kb + tg + 4) * LP + m]);
            af[mt][3] = __float_as_uint(Ab[(kb + tg + 4) * LP + m + 8]);
        }
#pragma unroll
        for (int nt = 0; nt < NT; nt++) {
            const int n = wn * NT * 8 + nt * 8 + g;
            bf[nt][0] = __float_as_uint(Bb[(kb + tg) * LP + n]);
            bf[nt][1] = __float_as_uint(Bb[(kb + tg + 4) * LP + n]);
        }
#pragma unroll
        for (int mt = 0; mt < MT; mt++)
#pragma unroll
            for (int nt = 0; nt < NT; nt++) mma8(acc[mt][nt], af[mt], bf[nt]);
    };
    auto comboB = [&](const uint32_t* Ab, const uint32_t* Bb) {
        uint32_t af[MT][4], bf[NT][2];
#pragma unroll
        for (int mt = 0; mt < MT; mt++) {
            const int m = wm * MT * 16 + mt * 16 + g;
            af[mt][0] = Ab[tg * LP + m];
            af[mt][1] = Ab[tg * LP + m + 8];
            af[mt][2] = Ab[(tg + 4) * LP + m];
            af[mt][3] = Ab[(tg + 4) * LP + m + 8];
        }
#pragma unroll
        for (int nt = 0; nt < NT; nt++) {
            const int n = wn * NT * 8 + nt * 8 + g;
            bf[nt][0] = Bb[tg * LP + n];
            bf[nt][1] = Bb[(tg + 4) * LP + n];
        }
#pragma unroll
        for (int mt = 0; mt < MT; mt++)
#pragma unroll
            for (int nt = 0; nt < NT; nt++) mma16bf(acc[mt][nt], af[mt], bf[nt]);
    };

    loadA(0);
    loadB(0);
    stageAll(0);
    __syncthreads();

    constexpr int KCH = KTOT / 16;
    int buf = 0;
#pragma unroll 1
    for (int kc = 0; kc < KCH; kc++) {
        if (kc + 1 < KCH) {
            loadA((kc + 1) * 16);
            loadB((kc + 1) * 16);
        }
        comboT(AsH + buf * BUF, BsH + buf * BUF, 0);
        comboT(AsH + buf * BUF, BsH + buf * BUF, 8);
        if constexpr (SPLIT) {
            comboB(AbfH + buf * BUFB, BbfL + buf * BUFB);
            comboB(AbfL + buf * BUFB, BbfH + buf * BUFB);
        }
        if (kc + 1 < KCH) stageAll(buf ^ 1);
        __syncthreads();
        buf ^= 1;
    }

    // ---------------- epilogue ----------------
#pragma unroll
    for (int mt = 0; mt < MT; mt++) {
#pragma unroll
        for (int nt = 0; nt < NT; nt++) {
            const int r0 = m0 + wm * MT * 16 + mt * 16 + g;
            const int r1 = r0 + 8;
            const int c = n0 + wn * NT * 8 + nt * 8 + tg * 2;
            const float* a = acc[mt][nt];
            if constexpr (CMODE == 0) {
                *(float2*)(Ch + z * cZ + (size_t)r0 * LDC + c) =
                    make_float2(scale * a[0], scale * a[1]);
                *(float2*)(Ch + z * cZ + (size_t)r1 * LDC + c) =
                    make_float2(scale * a[2], scale * a[3]);
            } else {
                const size_t o0 = ((size_t)(r0 >> 10) << 20) | ((size_t)(c >> 6) << 16) |
                                  ((size_t)(r0 & 1023) << 6) | (size_t)(c & 63);
                const size_t o1 = ((size_t)(r1 >> 10) << 20) | ((size_t)(c >> 6) << 16) |
                                  ((size_t)(r1 & 1023) << 6) | (size_t)(c & 63);
                if constexpr (CMODE == 2) {
                    *(float2*)(Ch + o0) = make_float2(scale * a[0], scale * a[1]);
                    *(float2*)(Ch + o1) = make_float2(scale * a[2], scale * a[3]);
                } else {
                    float h0 = to_tf32(a[0]), h1 = to_tf32(a[1]);
                    float h2 = to_tf32(a[2]), h3 = to_tf32(a[3]);
                    *(float2*)(Ch + o0) = make_float2(h0, h1);
                    *(float2*)(Ch + o1) = make_float2(h2, h3);
                    *(uint32_t*)(Cbh + o0) = packbf(h0, h1);
                    *(uint32_t*)(Cbh + o1) = packbf(h2, h3);
                    *(uint32_t*)(Cbl + o0) = packbf(a[0] - h0, a[1] - h1);
                    *(uint32_t*)(Cbl + o1) = packbf(a[2] - h2, a[3] - h3);
                }
            }
        }
    }
}

// ============================ softmax over batch axis (writes tf32-rounded P) ============================
__global__ void softmax_b(float* __restrict__ S) {
    const size_t idx = ((size_t)blockIdx.x * 256 + threadIdx.x) * 4;
    float v[8][4];
#pragma unroll
    for (int b = 0; b < 8; b++) {
        float4 x = *(const float4*)(S + (size_t)b * 16777216u + idx);
        v[b][0] = x.x; v[b][1] = x.y; v[b][2] = x.z; v[b][3] = x.w;
    }
#pragma unroll
    for (int c = 0; c < 4; c++) {
        float mx = v[0][c];
#pragma unroll
        for (int b = 1; b < 8; b++) mx = fmaxf(mx, v[b][c]);
        float sum = 0.f;
#pragma unroll
        for (int b = 0; b < 8; b++) {
            v[b][c] = __expf(v[b][c] - mx);
            sum += v[b][c];
        }
        const float inv = 1.0f / sum;
#pragma unroll
        for (int b = 0; b < 8; b++) v[b][c] = to_tf32(v[b][c] * inv);
    }
#pragma unroll
    for (int b = 0; b < 8; b++) {
        *(float4*)(S + (size_t)b * 16777216u + idx) =
            make_float4(v[b][0], v[b][1], v[b][2], v[b][3]);
    }
}

// ============================ launcher ============================
extern "C" void kernel_launch(void* const* d_in, const int* in_sizes, int n_in,
                              void* d_out, int out_size) {
    const float* query = (const float*)d_in[0];
    const float* key_ = (const float*)d_in[1];
    const float* value = (const float*)d_in[2];
    const float* q_w = (const float*)d_in[3];
    const float* k_w = (const float*)d_in[4];
    const float* v_w = (const float*)d_in[5];
    const float* o_w = (const float*)d_in[6];
    float* out = (float*)d_out;

    float *qh, *kh, *qwh, *kwh, *wqh, *wkh, *wv, *sc, *hd;
    uint16_t *qbh, *qbl, *kbh, *kbl, *qwbh, *qwbl, *kwbh, *kwbl;
    uint16_t *wqbh, *wqbl, *wkbh, *wkbl;
    cudaGetSymbolAddress((void**)&qh, g_qh);
    cudaGetSymbolAddress((void**)&qbh, g_qbh);   cudaGetSymbolAddress((void**)&qbl, g_qbl);
    cudaGetSymbolAddress((void**)&kh, g_kh);
    cudaGetSymbolAddress((void**)&kbh, g_kbh);   cudaGetSymbolAddress((void**)&kbl, g_kbl);
    cudaGetSymbolAddress((void**)&qwh, g_qwh);
    cudaGetSymbolAddress((void**)&qwbh, g_qwbh); cudaGetSymbolAddress((void**)&qwbl, g_qwbl);
    cudaGetSymbolAddress((void**)&kwh, g_kwh);
    cudaGetSymbolAddress((void**)&kwbh, g_kwbh); cudaGetSymbolAddress((void**)&kwbl, g_kwbl);
    cudaGetSymbolAddress((void**)&wqh, g_wqh);
    cudaGetSymbolAddress((void**)&wqbh, g_wqbh); cudaGetSymbolAddress((void**)&wqbl, g_wqbl);
    cudaGetSymbolAddress((void**)&wkh, g_wkh);
    cudaGetSymbolAddress((void**)&wkbh, g_wkbh); cudaGetSymbolAddress((void**)&wkbl, g_wkbl);
    cudaGetSymbolAddress((void**)&wv, g_wv);
    cudaGetSymbolAddress((void**)&sc, g_scores);
    cudaGetSymbolAddress((void**)&hd, g_heads);

    auto kQK = mma_gemm<1024, 128, true, 1, 1, false, false, 1024, 64, 0>;
    auto kV  = mma_gemm<1024, 128, false, 1, 2, true, true, 1024, 64, 0>;
    auto kS  = mma_gemm<64, 128, true, 2, 0, false, false, 64, 64, 1024>;
    auto kPV = mma_gemm<1024, 64, false, 0, 0, false, true, 1024, 64, 64>;
    auto kO  = mma_gemm<1024, 128, false, 0, 0, true, true, 1024, 1024, 1024>;

    const int SM_SPLIT = 4 * 16 * 132 * 4 + 8 * 8 * 132 * 4;  // 67584 B
    const int SM_PLAIN = 4 * 16 * 132 * 4;                    // 33792 B
    cudaFuncSetAttribute((const void*)kQK, cudaFuncAttributeMaxDynamicSharedMemorySize, SM_SPLIT);
    cudaFuncSetAttribute((const void*)kV,  cudaFuncAttributeMaxDynamicSharedMemorySize, SM_PLAIN);
    cudaFuncSetAttribute((const void*)kS,  cudaFuncAttributeMaxDynamicSharedMemorySize, SM_SPLIT);
    cudaFuncSetAttribute((const void*)kPV, cudaFuncAttributeMaxDynamicSharedMemorySize, SM_PLAIN);
    cudaFuncSetAttribute((const void*)kO,  cudaFuncAttributeMaxDynamicSharedMemorySize, SM_PLAIN);

    // 1) splits: tf32 hi + bf16(hi) + bf16(residual)
    split3<<<4096, 256>>>(query, qh, qbh, qbl);
    split3<<<4096, 256>>>(key_, kh, kbh, kbl);
    split3<<<512, 256>>>(q_w, qwh, qwbh, qwbl);
    split3<<<512, 256>>>(k_w, kwh, kwbh, kwbl);

    // 2) Q/K projections (tf32 main + bf16 corrections) -> [b,h,i,s] hi + bf16 pair
    kQK<<<dim3(8, 64, 1), 256, SM_SPLIT>>>(qh, qbh, qbl, qwh, qwbh, qwbl,
                                           wqh, wqbh, wqbl, 0, 0, 0, 1.0f);
    kQK<<<dim3(8, 64, 1), 256, SM_SPLIT>>>(kh, kbh, kbl, kwh, kwbh, kwbl,
                                           wkh, wkbh, wkbl, 0, 0, 0, 1.0f);

    // 3) V projection (1xtf32) -> [b,h,j,s]
    kV<<<dim3(8, 64, 1), 256, SM_PLAIN>>>(value, nullptr, nullptr, v_w, nullptr, nullptr,
                                          wv, nullptr, nullptr, 0, 0, 0, 1.0f);

    // 4) scores = 0.25 * WQ WK^T per (b,h)
    kS<<<dim3(8, 8, 128), 256, SM_SPLIT>>>(wqh, wqbh, wqbl, wkh, wkbh, wkbl,
                                           sc, nullptr, nullptr, 65536, 65536, 1048576, 0.25f);

    // 5) softmax over batch axis (pre-rounds P to tf32)
    softmax_b<<<16384, 256>>>(sc);

    // 6) heads = P * WV per (b,h)
    kPV<<<dim3(1, 8, 128), 256, SM_PLAIN>>>(sc, nullptr, nullptr, wv, nullptr, nullptr,
                                            hd, nullptr, nullptr, 1048576, 65536, 65536, 1.0f);

    // 7) out = heads_flat x o_w
    kO<<<dim3(8, 64, 1), 256, SM_PLAIN>>>(hd, nullptr, nullptr, o_w, nullptr, nullptr,
                                          out, nullptr, nullptr, 0, 0, 0, 1.0f);
}

// round 5
// speedup vs baseline: 1.2504x; 1.2504x over previous
#include <cuda_runtime.h>
#include <cstdint>

// ============================ helpers ============================
__device__ __forceinline__ float to_tf32(float x) {
    uint32_t u;
    asm("cvt.rna.tf32.f32 %0, %1;" : "=r"(u) : "f"(x));
    return __uint_as_float(u);
}
__device__ __forceinline__ uint32_t smem_u32(const void* p) {
    uint32_t a;
    asm("{ .reg .u64 t; cvta.to.shared.u64 t, %1; cvt.u32.u64 %0, t; }" : "=r"(a) : "l"(p));
    return a;
}
__device__ __forceinline__ void cp16(uint32_t dst, const void* src) {
    asm volatile("cp.async.cg.shared.global [%0], [%1], 16;" :: "r"(dst), "l"(src));
}
#define CP_COMMIT() asm volatile("cp.async.commit_group;" ::: "memory")
#define CP_WAIT1() asm volatile("cp.async.wait_group 1;" ::: "memory")

__device__ __forceinline__ void mma8(float* c, const uint32_t* a, const uint32_t* b) {
    asm volatile(
        "mma.sync.aligned.m16n8k8.row.col.f32.tf32.tf32.f32 "
        "{%0,%1,%2,%3}, {%4,%5,%6,%7}, {%8,%9}, {%0,%1,%2,%3};"
        : "+f"(c[0]), "+f"(c[1]), "+f"(c[2]), "+f"(c[3])
        : "r"(a[0]), "r"(a[1]), "r"(a[2]), "r"(a[3]), "r"(b[0]), "r"(b[1]));
}

// ============================ device globals ============================
__device__ float g_qh[8388608], g_ql[8388608];     // query hi/lo
__device__ float g_kh[8388608], g_kl[8388608];     // key hi/lo
__device__ float g_v32[8388608];                   // value tf32-rounded
__device__ float g_qwTh[1048576], g_qwTl[1048576]; // q_w^T [n=h*64+s][k] hi/lo
__device__ float g_kwTh[1048576], g_kwTl[1048576];
__device__ float g_vwT[1048576];                   // v_w^T rounded
__device__ float g_owT[1048576];                   // o_w^T rounded
__device__ float g_wqh[8388608], g_wql[8388608];   // projected Q hi/lo [b,h,i,s]
__device__ float g_wkh[8388608], g_wkl[8388608];
__device__ float g_wvT[8388608];                   // projected V^T [b,h,s,j]
__device__ float g_scores[134217728];              // [b,h,i,j]
__device__ float g_heads[8388608];                 // [b,h,i,s]

// ============================ prep kernels ============================
__global__ void split_hl(const float* __restrict__ x, float* __restrict__ hi,
                         float* __restrict__ lo) {
    size_t i = ((size_t)blockIdx.x * 256 + threadIdx.x) * 4;
    float4 v = *(const float4*)(x + i);
    float4 h, l;
    h.x = to_tf32(v.x); l.x = to_tf32(v.x - h.x);
    h.y = to_tf32(v.y); l.y = to_tf32(v.y - h.y);
    h.z = to_tf32(v.z); l.z = to_tf32(v.z - h.z);
    h.w = to_tf32(v.w); l.w = to_tf32(v.w - h.w);
    *(float4*)(hi + i) = h;
    *(float4*)(lo + i) = l;
}
__global__ void round_t(const float* __restrict__ x, float* __restrict__ y) {
    size_t i = ((size_t)blockIdx.x * 256 + threadIdx.x) * 4;
    float4 v = *(const float4*)(x + i);
    v.x = to_tf32(v.x); v.y = to_tf32(v.y); v.z = to_tf32(v.z); v.w = to_tf32(v.w);
    *(float4*)(y + i) = v;
}
// in: [z][1024 k][S s] -> outH/outL[(z*S + s)][1024 k]  (hi/lo split optional)
template <bool SPLIT>
__global__ void trans_w(const float* __restrict__ in, float* __restrict__ oh,
                        float* __restrict__ ol, int S, size_t inZ) {
    __shared__ float sm[32][33];
    const int tx = threadIdx.x & 31, ty = threadIdx.x >> 5;
    const int k0 = blockIdx.x * 32, s0 = blockIdx.y * 32;
    const size_t z = blockIdx.z;
    const float* src = in + z * inZ;
#pragma unroll
    for (int j = 0; j < 4; j++)
        sm[ty + j * 8][tx] = src[(size_t)(k0 + ty + j * 8) * S + s0 + tx];
    __syncthreads();
#pragma unroll
    for (int j = 0; j < 4; j++) {
        const int s = s0 + ty + j * 8;
        float v = sm[tx][ty + j * 8];
        float h = to_tf32(v);
        oh[(z * S + s) * 1024 + k0 + tx] = h;
        if (SPLIT) ol[(z * S + s) * 1024 + k0 + tx] = to_tf32(v - h);
    }
}

// ============================ universal cp.async tf32 GEMM ============================
// C[128 x NTILE] = A[128 x KTOT] * B^T   (A: [m][k] row-major, B: [n][k] row-major)
// SPLIT: acc = Ah*Bh + Ah*Bl + Al*Bh  (tf32x3)
// CMODE 0: C + z*cZ + r*LDC + c (opt ROUND, scale)
// CMODE 1: packed [b,h,i,s] from global (r,c); write hi/lo pair
// CMODE 3: packed transposed [b,h,s,j] from (r=bj, c=hs); rounded
template <int KTOT, int NTILE, bool SPLIT, int CMODE, bool ROUND, int LDA, int LDB,
          int LDC, int MINCTA>
__global__ void __launch_bounds__(256, MINCTA) gemm(
    const float* __restrict__ Ah, const float* __restrict__ Al,
    const float* __restrict__ Bh, const float* __restrict__ Bl,
    float* __restrict__ C0, float* __restrict__ C1,
    size_t aZ, size_t bZ, size_t cZ, float scale) {
    extern __shared__ float sm[];
    constexpr int LP = 20;                     // 16 k + 4 pad: conflict-free frags
    constexpr int HALF = (128 + NTILE) * LP;   // floats, hi half of one stage
    constexpr int SZ = (SPLIT ? 2 : 1) * HALF; // floats per stage
    constexpr int KCH = KTOT / 16;

    const int t = threadIdx.x, lane = t & 31, wid = t >> 5;
    const int g = lane >> 2, tg = lane & 3;
    constexpr int WARP_M = (NTILE == 128) ? 2 : 4;
    constexpr int WARP_N = 8 / WARP_M;
    constexpr int MT = 128 / (WARP_M * 16);
    constexpr int NT = NTILE / (WARP_N * 8);
    const int wm = (WARP_N == 4) ? (wid >> 2) : (wid >> 1);
    const int wn = (WARP_N == 4) ? (wid & 3) : (wid & 1);
    const int m0 = blockIdx.y * 128, n0 = blockIdx.x * NTILE;
    const size_t z = blockIdx.z;
    const float* pAh = Ah + z * aZ;
    const float* pBh = Bh + z * bZ;
    const float* pAl = SPLIT ? Al + z * aZ : nullptr;
    const float* pBl = SPLIT ? Bl + z * bZ : nullptr;
    const uint32_t sb = smem_u32(sm);

    const int crow = t >> 2, cseg = (t & 3) * 4;

    auto issue = [&](int kc, int stg) {
        if (kc < KCH) {
            const int k0 = kc * 16;
            const uint32_t base = sb + stg * SZ * 4;
#pragma unroll
            for (int it = 0; it < 2; it++) {
                const int row = crow + it * 64;
                cp16(base + (row * LP + cseg) * 4,
                     pAh + (size_t)(m0 + row) * LDA + k0 + cseg);
            }
#pragma unroll
            for (int it = 0; it < NTILE / 64; it++) {
                const int row = crow + it * 64;
                cp16(base + ((128 + row) * LP + cseg) * 4,
                     pBh + (size_t)(n0 + row) * LDB + k0 + cseg);
            }
            if constexpr (SPLIT) {
                const uint32_t b2 = base + HALF * 4;
#pragma unroll
                for (int it = 0; it < 2; it++) {
                    const int row = crow + it * 64;
                    cp16(b2 + (row * LP + cseg) * 4,
                         pAl + (size_t)(m0 + row) * LDA + k0 + cseg);
                }
#pragma unroll
                for (int it = 0; it < NTILE / 64; it++) {
                    const int row = crow + it * 64;
                    cp16(b2 + ((128 + row) * LP + cseg) * 4,
                         pBl + (size_t)(n0 + row) * LDB + k0 + cseg);
                }
            }
        }
        CP_COMMIT();
    };

    float acc[MT][NT][4] = {};

    issue(0, 0);
    issue(1, 1);

    int stg = 0;
#pragma unroll 1
    for (int kc = 0; kc < KCH; kc++) {
        CP_WAIT1();
        __syncthreads();
        issue(kc + 2, (stg + 2) % 3);

        const float* SA = sm + stg * SZ;
        const float* SB = SA + 128 * LP;
        const float* SAl = SA + HALF;
        const float* SBl = SAl + 128 * LP;

#pragma unroll
        for (int kb = 0; kb < 16; kb += 8) {
            uint32_t ah[MT][4], bh[NT][2];
#pragma unroll
            for (int mt = 0; mt < MT; mt++) {
                const int m = wm * MT * 16 + mt * 16 + g;
                ah[mt][0] = __float_as_uint(SA[m * LP + kb + tg]);
                ah[mt][1] = __float_as_uint(SA[(m + 8) * LP + kb + tg]);
                ah[mt][2] = __float_as_uint(SA[m * LP + kb + tg + 4]);
                ah[mt][3] = __float_as_uint(SA[(m + 8) * LP + kb + tg + 4]);
            }
#pragma unroll
            for (int nt = 0; nt < NT; nt++) {
                const int n = wn * NT * 8 + nt * 8 + g;
                bh[nt][0] = __float_as_uint(SB[n * LP + kb + tg]);
                bh[nt][1] = __float_as_uint(SB[n * LP + kb + tg + 4]);
            }
            if constexpr (SPLIT) {
                uint32_t al[MT][4], bl[NT][2];
#pragma unroll
                for (int mt = 0; mt < MT; mt++) {
                    const int m = wm * MT * 16 + mt * 16 + g;
                    al[mt][0] = __float_as_uint(SAl[m * LP + kb + tg]);
                    al[mt][1] = __float_as_uint(SAl[(m + 8) * LP + kb + tg]);
                    al[mt][2] = __float_as_uint(SAl[m * LP + kb + tg + 4]);
                    al[mt][3] = __float_as_uint(SAl[(m + 8) * LP + kb + tg + 4]);
                }
#pragma unroll
                for (int nt = 0; nt < NT; nt++) {
                    const int n = wn * NT * 8 + nt * 8 + g;
                    bl[nt][0] = __float_as_uint(SBl[n * LP + kb + tg]);
                    bl[nt][1] = __float_as_uint(SBl[n * LP + kb + tg + 4]);
                }
#pragma unroll
                for (int mt = 0; mt < MT; mt++)
#pragma unroll
                    for (int nt = 0; nt < NT; nt++) {
                        mma8(acc[mt][nt], ah[mt], bh[nt]);
                        mma8(acc[mt][nt], ah[mt], bl[nt]);
                        mma8(acc[mt][nt], al[mt], bh[nt]);
                    }
            } else {
#pragma unroll
                for (int mt = 0; mt < MT; mt++)
#pragma unroll
                    for (int nt = 0; nt < NT; nt++) mma8(acc[mt][nt], ah[mt], bh[nt]);
            }
        }
        stg = (stg + 1) % 3;
    }

    // ---------------- epilogue ----------------
#pragma unroll
    for (int mt = 0; mt < MT; mt++) {
#pragma unroll
        for (int nt = 0; nt < NT; nt++) {
            const int r0 = m0 + wm * MT * 16 + mt * 16 + g;
            const int r1 = r0 + 8;
            const int c = n0 + wn * NT * 8 + nt * 8 + tg * 2;
            const float* a = acc[mt][nt];
            if constexpr (CMODE == 0) {
                float v0 = scale * a[0], v1 = scale * a[1];
                float v2 = scale * a[2], v3 = scale * a[3];
                if (ROUND) {
                    v0 = to_tf32(v0); v1 = to_tf32(v1);
                    v2 = to_tf32(v2); v3 = to_tf32(v3);
                }
                *(float2*)(C0 + z * cZ + (size_t)r0 * LDC + c) = make_float2(v0, v1);
                *(float2*)(C0 + z * cZ + (size_t)r1 * LDC + c) = make_float2(v2, v3);
            } else if constexpr (CMODE == 1) {
                const size_t o0 = ((size_t)(r0 >> 10) << 20) | ((size_t)(c >> 6) << 16) |
                                  ((size_t)(r0 & 1023) << 6) | (size_t)(c & 63);
                const size_t o1 = ((size_t)(r1 >> 10) << 20) | ((size_t)(c >> 6) << 16) |
                                  ((size_t)(r1 & 1023) << 6) | (size_t)(c & 63);
                float h0 = to_tf32(a[0]), h1 = to_tf32(a[1]);
                float h2 = to_tf32(a[2]), h3 = to_tf32(a[3]);
                *(float2*)(C0 + o0) = make_float2(h0, h1);
                *(float2*)(C0 + o1) = make_float2(h2, h3);
                *(float2*)(C1 + o0) = make_float2(to_tf32(a[0] - h0), to_tf32(a[1] - h1));
                *(float2*)(C1 + o1) = make_float2(to_tf32(a[2] - h2), to_tf32(a[3] - h3));
            } else {  // CMODE 3: transposed packed [b,h,s,j], rounded
                const size_t base0 = ((size_t)(r0 >> 10) << 20) | ((size_t)(c >> 6) << 16);
#pragma unroll
                for (int q = 0; q < 2; q++) {
                    const int cc = c + q;
                    const size_t sOff = ((size_t)(cc & 63) << 10);
                    C0[base0 | sOff | (size_t)(r0 & 1023)] = to_tf32(a[q]);
                    C0[base0 | sOff | (size_t)(r1 & 1023)] = to_tf32(a[2 + q]);
                }
            }
        }
    }
}

// ============================ softmax over batch axis (rounds P to tf32) ============================
__global__ void softmax_b(float* __restrict__ S) {
    const size_t idx = ((size_t)blockIdx.x * 256 + threadIdx.x) * 4;
    float v[8][4];
#pragma unroll
    for (int b = 0; b < 8; b++) {
        float4 x = *(const float4*)(S + (size_t)b * 16777216u + idx);
        v[b][0] = x.x; v[b][1] = x.y; v[b][2] = x.z; v[b][3] = x.w;
    }
#pragma unroll
    for (int c = 0; c < 4; c++) {
        float mx = v[0][c];
#pragma unroll
        for (int b = 1; b < 8; b++) mx = fmaxf(mx, v[b][c]);
        float sum = 0.f;
#pragma unroll
        for (int b = 0; b < 8; b++) {
            v[b][c] = __expf(v[b][c] - mx);
            sum += v[b][c];
        }
        const float inv = 1.0f / sum;
#pragma unroll
        for (int b = 0; b < 8; b++) v[b][c] = to_tf32(v[b][c] * inv);
    }
#pragma unroll
    for (int b = 0; b < 8; b++) {
        *(float4*)(S + (size_t)b * 16777216u + idx) =
            make_float4(v[b][0], v[b][1], v[b][2], v[b][3]);
    }
}

// ============================ launcher ============================
extern "C" void kernel_launch(void* const* d_in, const int* in_sizes, int n_in,
                              void* d_out, int out_size) {
    const float* query = (const float*)d_in[0];
    const float* key_ = (const float*)d_in[1];
    const float* value = (const float*)d_in[2];
    const float* q_w = (const float*)d_in[3];
    const float* k_w = (const float*)d_in[4];
    const float* v_w = (const float*)d_in[5];
    const float* o_w = (const float*)d_in[6];
    float* out = (float*)d_out;

    float *qh, *ql, *kh, *kl, *v32, *qwTh, *qwTl, *kwTh, *kwTl, *vwT, *owT;
    float *wqh, *wql, *wkh, *wkl, *wvT, *sc, *hd;
    cudaGetSymbolAddress((void**)&qh, g_qh);     cudaGetSymbolAddress((void**)&ql, g_ql);
    cudaGetSymbolAddress((void**)&kh, g_kh);     cudaGetSymbolAddress((void**)&kl, g_kl);
    cudaGetSymbolAddress((void**)&v32, g_v32);
    cudaGetSymbolAddress((void**)&qwTh, g_qwTh); cudaGetSymbolAddress((void**)&qwTl, g_qwTl);
    cudaGetSymbolAddress((void**)&kwTh, g_kwTh); cudaGetSymbolAddress((void**)&kwTl, g_kwTl);
    cudaGetSymbolAddress((void**)&vwT, g_vwT);   cudaGetSymbolAddress((void**)&owT, g_owT);
    cudaGetSymbolAddress((void**)&wqh, g_wqh);   cudaGetSymbolAddress((void**)&wql, g_wql);
    cudaGetSymbolAddress((void**)&wkh, g_wkh);   cudaGetSymbolAddress((void**)&wkl, g_wkl);
    cudaGetSymbolAddress((void**)&wvT, g_wvT);
    cudaGetSymbolAddress((void**)&sc, g_scores);
    cudaGetSymbolAddress((void**)&hd, g_heads);

    //                 KTOT NTILE SPLIT CMODE ROUND  LDA   LDB   LDC  MINCTA
    auto kQK = gemm<1024, 128, true,  1, false, 1024, 1024, 0,    1>;
    auto kV  = gemm<1024, 128, false, 3, true,  1024, 1024, 0,    2>;
    auto kS  = gemm<64,   128, true,  0, false, 64,   64,   1024, 1>;
    auto kPV = gemm<1024, 64,  false, 0, true,  1024, 1024, 64,   2>;
    auto kO  = gemm<1024, 128, false, 0, false, 1024, 1024, 1024, 2>;

    const int SM_SPLIT = 3 * 2 * 256 * 20 * 4;  // 122880
    const int SM_P128  = 3 * 256 * 20 * 4;      // 61440
    const int SM_P64   = 3 * 192 * 20 * 4;      // 46080
    cudaFuncSetAttribute((const void*)kQK, cudaFuncAttributeMaxDynamicSharedMemorySize, SM_SPLIT);
    cudaFuncSetAttribute((const void*)kV,  cudaFuncAttributeMaxDynamicSharedMemorySize, SM_P128);
    cudaFuncSetAttribute((const void*)kS,  cudaFuncAttributeMaxDynamicSharedMemorySize, SM_SPLIT);
    cudaFuncSetAttribute((const void*)kPV, cudaFuncAttributeMaxDynamicSharedMemorySize, SM_P64);
    cudaFuncSetAttribute((const void*)kO,  cudaFuncAttributeMaxDynamicSharedMemorySize, SM_P128);

    // prep
    split_hl<<<8192, 256>>>(query, qh, ql);
    split_hl<<<8192, 256>>>(key_, kh, kl);
    round_t<<<8192, 256>>>(value, v32);
    trans_w<true><<<dim3(32, 2, 16), 256>>>(q_w, qwTh, qwTl, 64, 65536);
    trans_w<true><<<dim3(32, 2, 16), 256>>>(k_w, kwTh, kwTl, 64, 65536);
    trans_w<false><<<dim3(32, 2, 16), 256>>>(v_w, vwT, nullptr, 64, 65536);
    trans_w<false><<<dim3(32, 32, 1), 256>>>(o_w, owT, nullptr, 1024, 0);

    // Q/K projections (tf32x3) -> packed [b,h,i,s] hi/lo
    kQK<<<dim3(8, 64, 1), 256, SM_SPLIT>>>(qh, ql, qwTh, qwTl, wqh, wql, 0, 0, 0, 1.0f);
    kQK<<<dim3(8, 64, 1), 256, SM_SPLIT>>>(kh, kl, kwTh, kwTl, wkh, wkl, 0, 0, 0, 1.0f);

    // V projection -> transposed packed [b,h,s,j], rounded
    kV<<<dim3(8, 64, 1), 256, SM_P128>>>(v32, nullptr, vwT, nullptr, wvT, nullptr,
                                         0, 0, 0, 1.0f);

    // scores = 0.25 * WQ WK^T per (b,h)  (tf32x3)
    kS<<<dim3(8, 8, 128), 256, SM_SPLIT>>>(wqh, wql, wkh, wkl, sc, nullptr,
                                           65536, 65536, 1048576, 0.25f);

    // softmax over batch axis (rounds to tf32)
    softmax_b<<<16384, 256>>>(sc);

    // heads = P @ WV per (b,h): A=P [i][j], B=wvT [s][j] -> packed [b,h,i,s], rounded
    kPV<<<dim3(1, 8, 128), 256, SM_P64>>>(sc, nullptr, wvT, nullptr, hd, nullptr,
                                          1048576, 65536, 65536, 1.0f);

    // out = heads_flat @ o_w: A=heads [8192][1024], B=owT [o][t]
    kO<<<dim3(8, 64, 1), 256, SM_P128>>>(hd, nullptr, owT, nullptr, out, nullptr,
                                         0, 0, 0, 1.0f);
}

// round 6
// speedup vs baseline: 1.4354x; 1.1480x over previous
#include <cuda_runtime.h>
#include <cstdint>

// ============================ helpers ============================
__device__ __forceinline__ float to_tf32(float x) {
    uint32_t u;
    asm("cvt.rna.tf32.f32 %0, %1;" : "=r"(u) : "f"(x));
    return __uint_as_float(u);
}
__device__ __forceinline__ uint32_t smem_u32(const void* p) {
    uint32_t a;
    asm("{ .reg .u64 t; cvta.to.shared.u64 t, %1; cvt.u32.u64 %0, t; }" : "=r"(a) : "l"(p));
    return a;
}
__device__ __forceinline__ void cp16(uint32_t dst, const void* src) {
    asm volatile("cp.async.cg.shared.global [%0], [%1], 16;" :: "r"(dst), "l"(src));
}
#define CP_COMMIT() asm volatile("cp.async.commit_group;" ::: "memory")
#define CP_WAIT1() asm volatile("cp.async.wait_group 1;" ::: "memory")

__device__ __forceinline__ void mma8(float* c, const uint32_t* a, const uint32_t* b) {
    asm volatile(
        "mma.sync.aligned.m16n8k8.row.col.f32.tf32.tf32.f32 "
        "{%0,%1,%2,%3}, {%4,%5,%6,%7}, {%8,%9}, {%0,%1,%2,%3};"
        : "+f"(c[0]), "+f"(c[1]), "+f"(c[2]), "+f"(c[3])
        : "r"(a[0]), "r"(a[1]), "r"(a[2]), "r"(a[3]), "r"(b[0]), "r"(b[1]));
}

// ============================ device globals ============================
__device__ float g_qkh[16777216], g_qkl[16777216];   // query|key hi/lo (8M each)
__device__ float g_v32[8388608];                     // value tf32-rounded
__device__ float g_qkwTh[2097152], g_qkwTl[2097152]; // q_w^T|k_w^T hi/lo (1M each)
__device__ float g_vwT[1048576];                     // v_w^T rounded
__device__ float g_owT[1048576];                     // o_w^T rounded
__device__ float g_wqkh[16777216], g_wqkl[16777216]; // projected Q|K hi/lo [b,h,i,s]
__device__ float g_wvT[8388608];                     // projected V^T [b,h,s,j]
__device__ float g_scores[134217728];                // [b,h,i,j]
__device__ float g_heads[8388608];                   // [b,h,i,s]

// ============================ prep: fused input split/round ============================
// y-dim selects: 0 = split query, 1 = split key, 2 = round value
__global__ void prep_inputs(const float* __restrict__ q, const float* __restrict__ k,
                            const float* __restrict__ v, float* __restrict__ qkh,
                            float* __restrict__ qkl, float* __restrict__ v32) {
    const int sel = blockIdx.y;
    const size_t i = ((size_t)blockIdx.x * 256 + threadIdx.x) * 4;
    if (sel == 2) {
        float4 x = *(const float4*)(v + i);
        x.x = to_tf32(x.x); x.y = to_tf32(x.y); x.z = to_tf32(x.z); x.w = to_tf32(x.w);
        *(float4*)(v32 + i) = x;
        return;
    }
    const float* src = (sel == 0) ? q : k;
    const size_t off = (size_t)sel * 16777216u / 2u;
    float4 x = *(const float4*)(src + i);
    float4 h, l;
    h.x = to_tf32(x.x); l.x = to_tf32(x.x - h.x);
    h.y = to_tf32(x.y); l.y = to_tf32(x.y - h.y);
    h.z = to_tf32(x.z); l.z = to_tf32(x.z - h.z);
    h.w = to_tf32(x.w); l.w = to_tf32(x.w - h.w);
    *(float4*)(qkh + off + i) = h;
    *(float4*)(qkl + off + i) = l;
}

// ============================ prep: fused weight transpose ============================
// z-dim: [0,16) q_w head (split), [16,32) k_w head (split), [32,48) v_w head (round)
__global__ void trans_qkv(const float* __restrict__ qw, const float* __restrict__ kw,
                          const float* __restrict__ vw, float* __restrict__ qkwTh,
                          float* __restrict__ qkwTl, float* __restrict__ vwT) {
    __shared__ float sm[32][33];
    const int tx = threadIdx.x & 31, ty = threadIdx.x >> 5;
    const int k0 = blockIdx.x * 32, s0 = blockIdx.y * 32;
    const int z = blockIdx.z;
    const int grp = z >> 4, h = z & 15;
    const float* src = (grp == 0 ? qw : grp == 1 ? kw : vw) + (size_t)h * 65536;
#pragma unroll
    for (int j = 0; j < 4; j++)
        sm[ty + j * 8][tx] = src[(size_t)(k0 + ty + j * 8) * 64 + s0 + tx];
    __syncthreads();
    if (grp < 2) {
        float* oh = qkwTh + (size_t)grp * 1048576;
        float* ol = qkwTl + (size_t)grp * 1048576;
#pragma unroll
        for (int j = 0; j < 4; j++) {
            const int s = s0 + ty + j * 8;
            float v = sm[tx][ty + j * 8];
            float hv = to_tf32(v);
            oh[(size_t)(h * 64 + s) * 1024 + k0 + tx] = hv;
            ol[(size_t)(h * 64 + s) * 1024 + k0 + tx] = to_tf32(v - hv);
        }
    } else {
#pragma unroll
        for (int j = 0; j < 4; j++) {
            const int s = s0 + ty + j * 8;
            vwT[(size_t)(h * 64 + s) * 1024 + k0 + tx] = to_tf32(sm[tx][ty + j * 8]);
        }
    }
}
// o_w [1024 t][1024 o] -> owT [o][t], rounded
__global__ void trans_ow(const float* __restrict__ in, float* __restrict__ outp) {
    __shared__ float sm[32][33];
    const int tx = threadIdx.x & 31, ty = threadIdx.x >> 5;
    const int k0 = blockIdx.x * 32, s0 = blockIdx.y * 32;
#pragma unroll
    for (int j = 0; j < 4; j++)
        sm[ty + j * 8][tx] = in[(size_t)(k0 + ty + j * 8) * 1024 + s0 + tx];
    __syncthreads();
#pragma unroll
    for (int j = 0; j < 4; j++)
        outp[(size_t)(s0 + ty + j * 8) * 1024 + k0 + tx] = to_tf32(sm[tx][ty + j * 8]);
}

// ============================ universal cp.async tf32 GEMM ============================
// C[128 x NTILE] = A[128 x KTOT] * B^T (both row-major over K)
// SPLIT: tf32x3 (AhBh + AhBl + AlBh), 2-stage pipeline, 2 CTAs/SM
// CMODE 0: C + z*cZ + r*LDC + c (opt ROUND, scale)
// CMODE 1: packed [b,h,i,s]; writes hi/lo pair (+z*cZ)
// CMODE 3: packed transposed [b,h,s,j]; rounded
template <int KTOT, int NTILE, bool SPLIT, int CMODE, bool ROUND, int LDA, int LDB,
          int LDC, int MINCTA, int STAGES>
__global__ void __launch_bounds__(256, MINCTA) gemm(
    const float* __restrict__ Ah, const float* __restrict__ Al,
    const float* __restrict__ Bh, const float* __restrict__ Bl,
    float* __restrict__ C0, float* __restrict__ C1,
    size_t aZ, size_t bZ, size_t cZ, float scale) {
    extern __shared__ float sm[];
    constexpr int LP = 20;
    constexpr int HALF = (128 + NTILE) * LP;
    constexpr int SZ = (SPLIT ? 2 : 1) * HALF;
    constexpr int KCH = KTOT / 16;

    const int t = threadIdx.x, lane = t & 31, wid = t >> 5;
    const int g = lane >> 2, tg = lane & 3;
    constexpr int WARP_M = (NTILE == 128) ? 2 : 4;
    constexpr int WARP_N = 8 / WARP_M;
    constexpr int MT = 128 / (WARP_M * 16);
    constexpr int NT = NTILE / (WARP_N * 8);
    const int wm = (WARP_N == 4) ? (wid >> 2) : (wid >> 1);
    const int wn = (WARP_N == 4) ? (wid & 3) : (wid & 1);
    const int m0 = blockIdx.y * 128, n0 = blockIdx.x * NTILE;
    const size_t z = blockIdx.z;
    const float* pAh = Ah + z * aZ;
    const float* pBh = Bh + z * bZ;
    const float* pAl = SPLIT ? Al + z * aZ : nullptr;
    const float* pBl = SPLIT ? Bl + z * bZ : nullptr;
    if (CMODE != 0) { C0 += z * cZ; if (SPLIT && CMODE == 1) C1 += z * cZ; }
    const uint32_t sb = smem_u32(sm);

    const int crow = t >> 2, cseg = (t & 3) * 4;

    auto issue = [&](int kc, int stg) {
        if (kc < KCH) {
            const int k0 = kc * 16;
            const uint32_t base = sb + stg * SZ * 4;
#pragma unroll
            for (int it = 0; it < 2; it++) {
                const int row = crow + it * 64;
                cp16(base + (row * LP + cseg) * 4,
                     pAh + (size_t)(m0 + row) * LDA + k0 + cseg);
            }
#pragma unroll
            for (int it = 0; it < NTILE / 64; it++) {
                const int row = crow + it * 64;
                cp16(base + ((128 + row) * LP + cseg) * 4,
                     pBh + (size_t)(n0 + row) * LDB + k0 + cseg);
            }
            if constexpr (SPLIT) {
                const uint32_t b2 = base + HALF * 4;
#pragma unroll
                for (int it = 0; it < 2; it++) {
                    const int row = crow + it * 64;
                    cp16(b2 + (row * LP + cseg) * 4,
                         pAl + (size_t)(m0 + row) * LDA + k0 + cseg);
                }
#pragma unroll
                for (int it = 0; it < NTILE / 64; it++) {
                    const int row = crow + it * 64;
                    cp16(b2 + ((128 + row) * LP + cseg) * 4,
                         pBl + (size_t)(n0 + row) * LDB + k0 + cseg);
                }
            }
        }
        CP_COMMIT();
    };

    float acc[MT][NT][4] = {};

    auto compute = [&](int stg) {
        const float* SA = sm + stg * SZ;
        const float* SB = SA + 128 * LP;
        const float* SAl = SA + HALF;
        const float* SBl = SAl + 128 * LP;
#pragma unroll
        for (int kb = 0; kb < 16; kb += 8) {
            uint32_t ah[MT][4], bh[NT][2];
#pragma unroll
            for (int mt = 0; mt < MT; mt++) {
                const int m = wm * MT * 16 + mt * 16 + g;
                ah[mt][0] = __float_as_uint(SA[m * LP + kb + tg]);
                ah[mt][1] = __float_as_uint(SA[(m + 8) * LP + kb + tg]);
                ah[mt][2] = __float_as_uint(SA[m * LP + kb + tg + 4]);
                ah[mt][3] = __float_as_uint(SA[(m + 8) * LP + kb + tg + 4]);
            }
#pragma unroll
            for (int nt = 0; nt < NT; nt++) {
                const int n = wn * NT * 8 + nt * 8 + g;
                bh[nt][0] = __float_as_uint(SB[n * LP + kb + tg]);
                bh[nt][1] = __float_as_uint(SB[n * LP + kb + tg + 4]);
            }
#pragma unroll
            for (int mt = 0; mt < MT; mt++)
#pragma unroll
                for (int nt = 0; nt < NT; nt++) mma8(acc[mt][nt], ah[mt], bh[nt]);
            if constexpr (SPLIT) {
                uint32_t bl[NT][2];
#pragma unroll
                for (int nt = 0; nt < NT; nt++) {
                    const int n = wn * NT * 8 + nt * 8 + g;
                    bl[nt][0] = __float_as_uint(SBl[n * LP + kb + tg]);
                    bl[nt][1] = __float_as_uint(SBl[n * LP + kb + tg + 4]);
                }
#pragma unroll
                for (int mt = 0; mt < MT; mt++)
#pragma unroll
                    for (int nt = 0; nt < NT; nt++) mma8(acc[mt][nt], ah[mt], bl[nt]);
                uint32_t al[MT][4];
#pragma unroll
                for (int mt = 0; mt < MT; mt++) {
                    const int m = wm * MT * 16 + mt * 16 + g;
                    al[mt][0] = __float_as_uint(SAl[m * LP + kb + tg]);
                    al[mt][1] = __float_as_uint(SAl[(m + 8) * LP + kb + tg]);
                    al[mt][2] = __float_as_uint(SAl[m * LP + kb + tg + 4]);
                    al[mt][3] = __float_as_uint(SAl[(m + 8) * LP + kb + tg + 4]);
                }
#pragma unroll
                for (int mt = 0; mt < MT; mt++)
#pragma unroll
                    for (int nt = 0; nt < NT; nt++) mma8(acc[mt][nt], al[mt], bh[nt]);
            }
        }
    };

    issue(0, 0);
    issue(1, 1);
    int stg = 0;
#pragma unroll 1
    for (int kc = 0; kc < KCH; kc++) {
        CP_WAIT1();
        __syncthreads();
        if constexpr (STAGES == 2) {
            compute(stg);
            __syncthreads();
            issue(kc + 2, stg);
            stg ^= 1;
        } else {
            issue(kc + 2, (stg + 2) % 3);
            compute(stg);
            stg = (stg + 1) % 3;
        }
    }

    // ---------------- epilogue ----------------
#pragma unroll
    for (int mt = 0; mt < MT; mt++) {
#pragma unroll
        for (int nt = 0; nt < NT; nt++) {
            const int r0 = m0 + wm * MT * 16 + mt * 16 + g;
            const int r1 = r0 + 8;
            const int c = n0 + wn * NT * 8 + nt * 8 + tg * 2;
            const float* a = acc[mt][nt];
            if constexpr (CMODE == 0) {
                float v0 = scale * a[0], v1 = scale * a[1];
                float v2 = scale * a[2], v3 = scale * a[3];
                if (ROUND) {
                    v0 = to_tf32(v0); v1 = to_tf32(v1);
                    v2 = to_tf32(v2); v3 = to_tf32(v3);
                }
                *(float2*)(C0 + z * cZ + (size_t)r0 * LDC + c) = make_float2(v0, v1);
                *(float2*)(C0 + z * cZ + (size_t)r1 * LDC + c) = make_float2(v2, v3);
            } else if constexpr (CMODE == 1) {
                const size_t o0 = ((size_t)(r0 >> 10) << 20) | ((size_t)(c >> 6) << 16) |
                                  ((size_t)(r0 & 1023) << 6) | (size_t)(c & 63);
                const size_t o1 = ((size_t)(r1 >> 10) << 20) | ((size_t)(c >> 6) << 16) |
                                  ((size_t)(r1 & 1023) << 6) | (size_t)(c & 63);
                float h0 = to_tf32(a[0]), h1 = to_tf32(a[1]);
                float h2 = to_tf32(a[2]), h3 = to_tf32(a[3]);
                *(float2*)(C0 + o0) = make_float2(h0, h1);
                *(float2*)(C0 + o1) = make_float2(h2, h3);
                *(float2*)(C1 + o0) = make_float2(to_tf32(a[0] - h0), to_tf32(a[1] - h1));
                *(float2*)(C1 + o1) = make_float2(to_tf32(a[2] - h2), to_tf32(a[3] - h3));
            } else {  // CMODE 3
                const size_t base0 = ((size_t)(r0 >> 10) << 20) | ((size_t)(c >> 6) << 16);
#pragma unroll
                for (int q = 0; q < 2; q++) {
                    const int cc = c + q;
                    const size_t sOff = ((size_t)(cc & 63) << 10);
                    C0[base0 | sOff | (size_t)(r0 & 1023)] = to_tf32(a[q]);
                    C0[base0 | sOff | (size_t)(r1 & 1023)] = to_tf32(a[2 + q]);
                }
            }
        }
    }
}

// ============================ softmax over batch axis (rounds P to tf32) ============================
__global__ void softmax_b(float* __restrict__ S) {
    const size_t idx = ((size_t)blockIdx.x * 256 + threadIdx.x) * 4;
    float v[8][4];
#pragma unroll
    for (int b = 0; b < 8; b++) {
        float4 x = *(const float4*)(S + (size_t)b * 16777216u + idx);
        v[b][0] = x.x; v[b][1] = x.y; v[b][2] = x.z; v[b][3] = x.w;
    }
#pragma unroll
    for (int c = 0; c < 4; c++) {
        float mx = v[0][c];
#pragma unroll
        for (int b = 1; b < 8; b++) mx = fmaxf(mx, v[b][c]);
        float sum = 0.f;
#pragma unroll
        for (int b = 0; b < 8; b++) {
            v[b][c] = __expf(v[b][c] - mx);
            sum += v[b][c];
        }
        const float inv = 1.0f / sum;
#pragma unroll
        for (int b = 0; b < 8; b++) v[b][c] = to_tf32(v[b][c] * inv);
    }
#pragma unroll
    for (int b = 0; b < 8; b++) {
        *(float4*)(S + (size_t)b * 16777216u + idx) =
            make_float4(v[b][0], v[b][1], v[b][2], v[b][3]);
    }
}

// ============================ launcher ============================
extern "C" void kernel_launch(void* const* d_in, const int* in_sizes, int n_in,
                              void* d_out, int out_size) {
    const float* query = (const float*)d_in[0];
    const float* key_ = (const float*)d_in[1];
    const float* value = (const float*)d_in[2];
    const float* q_w = (const float*)d_in[3];
    const float* k_w = (const float*)d_in[4];
    const float* v_w = (const float*)d_in[5];
    const float* o_w = (const float*)d_in[6];
    float* out = (float*)d_out;

    float *qkh, *qkl, *v32, *qkwTh, *qkwTl, *vwT, *owT;
    float *wqkh, *wqkl, *wvT, *sc, *hd;
    cudaGetSymbolAddress((void**)&qkh, g_qkh);     cudaGetSymbolAddress((void**)&qkl, g_qkl);
    cudaGetSymbolAddress((void**)&v32, g_v32);
    cudaGetSymbolAddress((void**)&qkwTh, g_qkwTh); cudaGetSymbolAddress((void**)&qkwTl, g_qkwTl);
    cudaGetSymbolAddress((void**)&vwT, g_vwT);     cudaGetSymbolAddress((void**)&owT, g_owT);
    cudaGetSymbolAddress((void**)&wqkh, g_wqkh);   cudaGetSymbolAddress((void**)&wqkl, g_wqkl);
    cudaGetSymbolAddress((void**)&wvT, g_wvT);
    cudaGetSymbolAddress((void**)&sc, g_scores);
    cudaGetSymbolAddress((void**)&hd, g_heads);

    //                KTOT NTILE SPLIT CMODE ROUND  LDA   LDB   LDC  MINCTA STAGES
    auto kQK = gemm<1024, 128, true,  1, false, 1024, 1024, 0,    2, 2>;
    auto kV  = gemm<1024, 128, false, 3, true,  1024, 1024, 0,    2, 3>;
    auto kS  = gemm<64,   128, true,  0, false, 64,   64,   1024, 2, 2>;
    auto kPV = gemm<1024, 64,  false, 0, true,  1024, 1024, 64,   3, 3>;
    auto kO  = gemm<1024, 128, false, 0, false, 1024, 1024, 1024, 2, 3>;

    const int SM_SPLIT = 2 * 2 * 256 * 20 * 4;  // 81920 (2 stages, hi+lo)
    const int SM_P128  = 3 * 256 * 20 * 4;      // 61440
    const int SM_P64   = 3 * 192 * 20 * 4;      // 46080
    cudaFuncSetAttribute((const void*)kQK, cudaFuncAttributeMaxDynamicSharedMemorySize, SM_SPLIT);
    cudaFuncSetAttribute((const void*)kV,  cudaFuncAttributeMaxDynamicSharedMemorySize, SM_P128);
    cudaFuncSetAttribute((const void*)kS,  cudaFuncAttributeMaxDynamicSharedMemorySize, SM_SPLIT);
    cudaFuncSetAttribute((const void*)kPV, cudaFuncAttributeMaxDynamicSharedMemorySize, SM_P64);
    cudaFuncSetAttribute((const void*)kO,  cudaFuncAttributeMaxDynamicSharedMemorySize, SM_P128);

    // 1) prep (fused: q/k split + v round)
    prep_inputs<<<dim3(8192, 3), 256>>>(query, key_, value, qkh, qkl, v32);
    // 2) weight transposes (fused q_w/k_w/v_w; o_w separate)
    trans_qkv<<<dim3(32, 2, 48), 256>>>(q_w, k_w, v_w, qkwTh, qkwTl, vwT);
    trans_ow<<<dim3(32, 32), 256>>>(o_w, owT);

    // 3) Q+K projections in one launch (tf32x3) -> packed [b,h,i,s] hi/lo
    kQK<<<dim3(8, 64, 2), 256, SM_SPLIT>>>(qkh, qkl, qkwTh, qkwTl, wqkh, wqkl,
                                           8388608, 1048576, 8388608, 1.0f);

    // 4) V projection -> transposed packed [b,h,s,j], rounded
    kV<<<dim3(8, 64, 1), 256, SM_P128>>>(v32, nullptr, vwT, nullptr, wvT, nullptr,
                                         0, 0, 0, 1.0f);

    // 5) scores = 0.25 * WQ WK^T per (b,h)  (tf32x3)   [ncu -s 5 lands here]
    kS<<<dim3(8, 8, 128), 256, SM_SPLIT>>>(wqkh, wqkl, wqkh + 8388608, wqkl + 8388608,
                                           sc, nullptr, 65536, 65536, 1048576, 0.25f);

    // 6) softmax over batch axis (rounds to tf32)
    softmax_b<<<16384, 256>>>(sc);

    // 7) heads = P @ WV per (b,h) -> packed [b,h,i,s], rounded
    kPV<<<dim3(1, 8, 128), 256, SM_P64>>>(sc, nullptr, wvT, nullptr, hd, nullptr,
                                          1048576, 65536, 65536, 1.0f);

    // 8) out = heads_flat @ o_w
    kO<<<dim3(8, 64, 1), 256, SM_P128>>>(hd, nullptr, owT, nullptr, out, nullptr,
                                         0, 0, 0, 1.0f);
}

// round 7
// speedup vs baseline: 2.2637x; 1.5770x over previous
#include <cuda_runtime.h>
#include <cuda_fp16.h>
#include <cstdint>

// ============================ helpers ============================
__device__ __forceinline__ uint32_t smem_u32(const void* p) {
    uint32_t a;
    asm("{ .reg .u64 t; cvta.to.shared.u64 t, %1; cvt.u32.u64 %0, t; }" : "=r"(a) : "l"(p));
    return a;
}
__device__ __forceinline__ void cp16(uint32_t dst, const void* src) {
    asm volatile("cp.async.cg.shared.global [%0], [%1], 16;" :: "r"(dst), "l"(src));
}
#define CP_COMMIT() asm volatile("cp.async.commit_group;" ::: "memory")
#define CP_WAIT1() asm volatile("cp.async.wait_group 1;" ::: "memory")

__device__ __forceinline__ void mma16h(float* c, const uint32_t* a, const uint32_t* b) {
    asm volatile(
        "mma.sync.aligned.m16n8k16.row.col.f32.f16.f16.f32 "
        "{%0,%1,%2,%3}, {%4,%5,%6,%7}, {%8,%9}, {%0,%1,%2,%3};"
        : "+f"(c[0]), "+f"(c[1]), "+f"(c[2]), "+f"(c[3])
        : "r"(a[0]), "r"(a[1]), "r"(a[2]), "r"(a[3]), "r"(b[0]), "r"(b[1]));
}
__device__ __forceinline__ uint32_t pack2(float a, float b) {
    __half2 h = __floats2half2_rn(a, b);
    return *(uint32_t*)&h;
}

// ============================ device globals ============================
__device__ __half g_qkh[16777216], g_qkl[16777216];   // query|key hi/lo limbs
__device__ __half g_v32[8388608];                     // value fp16
__device__ __half g_qkwTh[2097152], g_qkwTl[2097152]; // q_w^T|k_w^T hi/lo
__device__ __half g_vwT[1048576];                     // v_w^T
__device__ __half g_owT[1048576];                     // o_w^T
__device__ __half g_wqkh[16777216], g_wqkl[16777216]; // projected Q|K hi/lo [b,h,i,s]
__device__ __half g_wvT[8388608];                     // projected V^T [b,h,s,j]
__device__ float g_scores[134217728];                 // [b,h,i,j] fp32
__device__ __half g_P[134217728];                     // softmax probs fp16
__device__ __half g_heads[8388608];                   // [b,h,i,s] fp16

// ============================ prep: input split/convert ============================
// y: 0 = split query, 1 = split key, 2 = convert value
__global__ void prep_inputs(const float* __restrict__ q, const float* __restrict__ k,
                            const float* __restrict__ v, __half* __restrict__ qkh,
                            __half* __restrict__ qkl, __half* __restrict__ v32) {
    const int sel = blockIdx.y;
    const size_t i = ((size_t)blockIdx.x * 256 + threadIdx.x) * 8;
    float x[8];
    const float* src = (sel == 0) ? q : (sel == 1) ? k : v;
    float4 v0 = *(const float4*)(src + i);
    float4 v1 = *(const float4*)(src + i + 4);
    x[0] = v0.x; x[1] = v0.y; x[2] = v0.z; x[3] = v0.w;
    x[4] = v1.x; x[5] = v1.y; x[6] = v1.z; x[7] = v1.w;
    if (sel == 2) {
        uint4 o;
        o.x = pack2(x[0], x[1]); o.y = pack2(x[2], x[3]);
        o.z = pack2(x[4], x[5]); o.w = pack2(x[6], x[7]);
        *(uint4*)(v32 + i) = o;
        return;
    }
    const size_t off = (size_t)sel * 8388608u;
    float h[8], l[8];
#pragma unroll
    for (int j = 0; j < 8; j++) {
        h[j] = __half2float(__float2half_rn(x[j]));
        l[j] = x[j] - h[j];
    }
    uint4 oh, ol;
    oh.x = pack2(h[0], h[1]); oh.y = pack2(h[2], h[3]);
    oh.z = pack2(h[4], h[5]); oh.w = pack2(h[6], h[7]);
    ol.x = pack2(l[0], l[1]); ol.y = pack2(l[2], l[3]);
    ol.z = pack2(l[4], l[5]); ol.w = pack2(l[6], l[7]);
    *(uint4*)(qkh + off + i) = oh;
    *(uint4*)(qkl + off + i) = ol;
}

// ============================ prep: weight transposes ============================
// z: [0,16) q_w (split), [16,32) k_w (split), [32,48) v_w
__global__ void trans_qkv(const float* __restrict__ qw, const float* __restrict__ kw,
                          const float* __restrict__ vw, __half* __restrict__ qkwTh,
                          __half* __restrict__ qkwTl, __half* __restrict__ vwT) {
    __shared__ float sm[32][33];
    const int tx = threadIdx.x & 31, ty = threadIdx.x >> 5;
    const int k0 = blockIdx.x * 32, s0 = blockIdx.y * 32;
    const int z = blockIdx.z;
    const int grp = z >> 4, h = z & 15;
    const float* src = (grp == 0 ? qw : grp == 1 ? kw : vw) + (size_t)h * 65536;
#pragma unroll
    for (int j = 0; j < 4; j++)
        sm[ty + j * 8][tx] = src[(size_t)(k0 + ty + j * 8) * 64 + s0 + tx];
    __syncthreads();
    if (grp < 2) {
        __half* oh = qkwTh + (size_t)grp * 1048576;
        __half* ol = qkwTl + (size_t)grp * 1048576;
#pragma unroll
        for (int j = 0; j < 4; j++) {
            const int s = s0 + ty + j * 8;
            float v = sm[tx][ty + j * 8];
            __half hv = __float2half_rn(v);
            oh[(size_t)(h * 64 + s) * 1024 + k0 + tx] = hv;
            ol[(size_t)(h * 64 + s) * 1024 + k0 + tx] =
                __float2half_rn(v - __half2float(hv));
        }
    } else {
#pragma unroll
        for (int j = 0; j < 4; j++) {
            const int s = s0 + ty + j * 8;
            vwT[(size_t)(h * 64 + s) * 1024 + k0 + tx] =
                __float2half_rn(sm[tx][ty + j * 8]);
        }
    }
}
__global__ void trans_ow(const float* __restrict__ in, __half* __restrict__ outp) {
    __shared__ float sm[32][33];
    const int tx = threadIdx.x & 31, ty = threadIdx.x >> 5;
    const int k0 = blockIdx.x * 32, s0 = blockIdx.y * 32;
#pragma unroll
    for (int j = 0; j < 4; j++)
        sm[ty + j * 8][tx] = in[(size_t)(k0 + ty + j * 8) * 1024 + s0 + tx];
    __syncthreads();
#pragma unroll
    for (int j = 0; j < 4; j++)
        outp[(size_t)(s0 + ty + j * 8) * 1024 + k0 + tx] =
            __float2half_rn(sm[tx][ty + j * 8]);
}

// ============================ fp16-limb mma GEMM ============================
// C[128 x NTILE] = A[128 x KTOT] * B^T (both [rows][k] fp16, k packed 2/word)
// SPLIT: AhBh + AhBl + AlBh (fp32 accumulate). 3-stage cp.async pipeline.
// CMODE 0: C + z*cZ + r*LDC + c, scaled; OUTH picks half vs float.
// CMODE 1: packed [b,h,i,s] hi/lo half pair (+z*cZ)
// CMODE 3: transposed packed [b,h,s,j] half
template <int KTOT, int NTILE, bool SPLIT, int CMODE, bool OUTH, int LDA, int LDB,
          int LDC, int MINCTA>
__global__ void __launch_bounds__(256, MINCTA) gemm(
    const __half* __restrict__ Ah, const __half* __restrict__ Al,
    const __half* __restrict__ Bh, const __half* __restrict__ Bl,
    void* __restrict__ C0, void* __restrict__ C1,
    size_t aZ, size_t bZ, size_t cZ, float scale) {
    extern __shared__ uint32_t smw[];
    constexpr int LPW = 12;                       // 8 data words (16 fp16) + 4 pad
    constexpr int HALFW = (128 + NTILE) * LPW;    // words per hi half-stage
    constexpr int SZW = (SPLIT ? 2 : 1) * HALFW;  // words per stage
    constexpr int KCH = KTOT / 16;

    const int t = threadIdx.x, lane = t & 31, wid = t >> 5;
    const int g = lane >> 2, tg = lane & 3;
    constexpr int WARP_M = (NTILE == 128) ? 2 : 4;
    constexpr int WARP_N = 8 / WARP_M;
    constexpr int MT = 128 / (WARP_M * 16);
    constexpr int NT = NTILE / (WARP_N * 8);
    const int wm = (WARP_N == 4) ? (wid >> 2) : (wid >> 1);
    const int wn = (WARP_N == 4) ? (wid & 3) : (wid & 1);
    const int m0 = blockIdx.y * 128, n0 = blockIdx.x * NTILE;
    const size_t z = blockIdx.z;
    const __half* pAh = Ah + z * aZ;
    const __half* pBh = Bh + z * bZ;
    const __half* pAl = SPLIT ? Al + z * aZ : nullptr;
    const __half* pBl = SPLIT ? Bl + z * bZ : nullptr;
    const uint32_t sb = smem_u32(smw);

    const int crow = t >> 1, cseg = t & 1;  // 128 rows x 2 segs

    auto issue = [&](int kc, int stg) {
        if (kc < KCH) {
            const int k0 = kc * 16;
            const uint32_t base = sb + stg * SZW * 4;
            // A rows (128)
            cp16(base + (crow * LPW + cseg * 4) * 4,
                 pAh + (size_t)(m0 + crow) * LDA + k0 + cseg * 8);
            // B rows (NTILE)
            if (NTILE == 128 || t < 128)
                cp16(base + ((128 + crow) * LPW + cseg * 4) * 4,
                     pBh + (size_t)(n0 + crow) * LDB + k0 + cseg * 8);
            if constexpr (SPLIT) {
                const uint32_t b2 = base + HALFW * 4;
                cp16(b2 + (crow * LPW + cseg * 4) * 4,
                     pAl + (size_t)(m0 + crow) * LDA + k0 + cseg * 8);
                if (NTILE == 128 || t < 128)
                    cp16(b2 + ((128 + crow) * LPW + cseg * 4) * 4,
                         pBl + (size_t)(n0 + crow) * LDB + k0 + cseg * 8);
            }
        }
        CP_COMMIT();
    };

    float acc[MT][NT][4] = {};

    auto compute = [&](int stg) {
        const uint32_t* SA = smw + stg * SZW;
        const uint32_t* SB = SA + 128 * LPW;
        const uint32_t* SAl = SA + HALFW;
        const uint32_t* SBl = SAl + 128 * LPW;
        uint32_t ah[MT][4], bh[NT][2];
#pragma unroll
        for (int mt = 0; mt < MT; mt++) {
            const int m = wm * MT * 16 + mt * 16 + g;
            ah[mt][0] = SA[m * LPW + tg];
            ah[mt][1] = SA[(m + 8) * LPW + tg];
            ah[mt][2] = SA[m * LPW + tg + 4];
            ah[mt][3] = SA[(m + 8) * LPW + tg + 4];
        }
#pragma unroll
        for (int nt = 0; nt < NT; nt++) {
            const int n = wn * NT * 8 + nt * 8 + g;
            bh[nt][0] = SB[n * LPW + tg];
            bh[nt][1] = SB[n * LPW + tg + 4];
        }
#pragma unroll
        for (int mt = 0; mt < MT; mt++)
#pragma unroll
            for (int nt = 0; nt < NT; nt++) mma16h(acc[mt][nt], ah[mt], bh[nt]);
        if constexpr (SPLIT) {
            uint32_t bl[NT][2];
#pragma unroll
            for (int nt = 0; nt < NT; nt++) {
                const int n = wn * NT * 8 + nt * 8 + g;
                bl[nt][0] = SBl[n * LPW + tg];
                bl[nt][1] = SBl[n * LPW + tg + 4];
            }
#pragma unroll
            for (int mt = 0; mt < MT; mt++)
#pragma unroll
                for (int nt = 0; nt < NT; nt++) mma16h(acc[mt][nt], ah[mt], bl[nt]);
            uint32_t al[MT][4];
#pragma unroll
            for (int mt = 0; mt < MT; mt++) {
                const int m = wm * MT * 16 + mt * 16 + g;
                al[mt][0] = SAl[m * LPW + tg];
                al[mt][1] = SAl[(m + 8) * LPW + tg];
                al[mt][2] = SAl[m * LPW + tg + 4];
                al[mt][3] = SAl[(m + 8) * LPW + tg + 4];
            }
#pragma unroll
            for (int mt = 0; mt < MT; mt++)
#pragma unroll
                for (int nt = 0; nt < NT; nt++) mma16h(acc[mt][nt], al[mt], bh[nt]);
        }
    };

    issue(0, 0);
    issue(1, 1);
    int stg = 0;
#pragma unroll 1
    for (int kc = 0; kc < KCH; kc++) {
        CP_WAIT1();
        __syncthreads();
        issue(kc + 2, (stg + 2) % 3);
        compute(stg);
        stg = (stg + 1) % 3;
    }

    // ---------------- epilogue ----------------
#pragma unroll
    for (int mt = 0; mt < MT; mt++) {
#pragma unroll
        for (int nt = 0; nt < NT; nt++) {
            const int r0 = m0 + wm * MT * 16 + mt * 16 + g;
            const int r1 = r0 + 8;
            const int c = n0 + wn * NT * 8 + nt * 8 + tg * 2;
            const float* a = acc[mt][nt];
            if constexpr (CMODE == 0) {
                if constexpr (OUTH) {
                    __half* Cp = (__half*)C0 + z * cZ;
                    *(__half2*)(Cp + (size_t)r0 * LDC + c) =
                        __floats2half2_rn(scale * a[0], scale * a[1]);
                    *(__half2*)(Cp + (size_t)r1 * LDC + c) =
                        __floats2half2_rn(scale * a[2], scale * a[3]);
                } else {
                    float* Cp = (float*)C0 + z * cZ;
                    *(float2*)(Cp + (size_t)r0 * LDC + c) =
                        make_float2(scale * a[0], scale * a[1]);
                    *(float2*)(Cp + (size_t)r1 * LDC + c) =
                        make_float2(scale * a[2], scale * a[3]);
                }
            } else if constexpr (CMODE == 1) {
                __half* Ch = (__half*)C0 + z * cZ;
                __half* Cl = (__half*)C1 + z * cZ;
                const size_t o0 = ((size_t)(r0 >> 10) << 20) | ((size_t)(c >> 6) << 16) |
                                  ((size_t)(r0 & 1023) << 6) | (size_t)(c & 63);
                const size_t o1 = ((size_t)(r1 >> 10) << 20) | ((size_t)(c >> 6) << 16) |
                                  ((size_t)(r1 & 1023) << 6) | (size_t)(c & 63);
                float h0 = __half2float(__float2half_rn(a[0]));
                float h1 = __half2float(__float2half_rn(a[1]));
                float h2 = __half2float(__float2half_rn(a[2]));
                float h3 = __half2float(__float2half_rn(a[3]));
                *(__half2*)(Ch + o0) = __floats2half2_rn(h0, h1);
                *(__half2*)(Ch + o1) = __floats2half2_rn(h2, h3);
                *(__half2*)(Cl + o0) = __floats2half2_rn(a[0] - h0, a[1] - h1);
                *(__half2*)(Cl + o1) = __floats2half2_rn(a[2] - h2, a[3] - h3);
            } else {  // CMODE 3: transposed packed [b,h,s,j]
                __half* Cp = (__half*)C0;
                const size_t base0 = ((size_t)(r0 >> 10) << 20) | ((size_t)(c >> 6) << 16);
#pragma unroll
                for (int q = 0; q < 2; q++) {
                    const int cc = c + q;
                    const size_t sOff = ((size_t)(cc & 63) << 10);
                    Cp[base0 | sOff | (size_t)(r0 & 1023)] = __float2half_rn(a[q]);
                    Cp[base0 | sOff | (size_t)(r1 & 1023)] = __float2half_rn(a[2 + q]);
                }
            }
        }
    }
}

// ============================ softmax over batch axis -> fp16 P ============================
__global__ void softmax_b(const float* __restrict__ S, __half* __restrict__ P) {
    const size_t idx = ((size_t)blockIdx.x * 256 + threadIdx.x) * 4;
    float v[8][4];
#pragma unroll
    for (int b = 0; b < 8; b++) {
        float4 x = *(const float4*)(S + (size_t)b * 16777216u + idx);
        v[b][0] = x.x; v[b][1] = x.y; v[b][2] = x.z; v[b][3] = x.w;
    }
#pragma unroll
    for (int c = 0; c < 4; c++) {
        float mx = v[0][c];
#pragma unroll
        for (int b = 1; b < 8; b++) mx = fmaxf(mx, v[b][c]);
        float sum = 0.f;
#pragma unroll
        for (int b = 0; b < 8; b++) {
            v[b][c] = __expf(v[b][c] - mx);
            sum += v[b][c];
        }
        const float inv = 1.0f / sum;
#pragma unroll
        for (int b = 0; b < 8; b++) v[b][c] *= inv;
    }
#pragma unroll
    for (int b = 0; b < 8; b++) {
        uint2 o;
        o.x = pack2(v[b][0], v[b][1]);
        o.y = pack2(v[b][2], v[b][3]);
        *(uint2*)(P + (size_t)b * 16777216u + idx) = o;
    }
}

// ============================ launcher ============================
extern "C" void kernel_launch(void* const* d_in, const int* in_sizes, int n_in,
                              void* d_out, int out_size) {
    const float* query = (const float*)d_in[0];
    const float* key_ = (const float*)d_in[1];
    const float* value = (const float*)d_in[2];
    const float* q_w = (const float*)d_in[3];
    const float* k_w = (const float*)d_in[4];
    const float* v_w = (const float*)d_in[5];
    const float* o_w = (const float*)d_in[6];
    float* out = (float*)d_out;

    __half *qkh, *qkl, *v32, *qkwTh, *qkwTl, *vwT, *owT;
    __half *wqkh, *wqkl, *wvT, *P, *hd;
    float* sc;
    cudaGetSymbolAddress((void**)&qkh, g_qkh);     cudaGetSymbolAddress((void**)&qkl, g_qkl);
    cudaGetSymbolAddress((void**)&v32, g_v32);
    cudaGetSymbolAddress((void**)&qkwTh, g_qkwTh); cudaGetSymbolAddress((void**)&qkwTl, g_qkwTl);
    cudaGetSymbolAddress((void**)&vwT, g_vwT);     cudaGetSymbolAddress((void**)&owT, g_owT);
    cudaGetSymbolAddress((void**)&wqkh, g_wqkh);   cudaGetSymbolAddress((void**)&wqkl, g_wqkl);
    cudaGetSymbolAddress((void**)&wvT, g_wvT);
    cudaGetSymbolAddress((void**)&sc, g_scores);
    cudaGetSymbolAddress((void**)&P, g_P);
    cudaGetSymbolAddress((void**)&hd, g_heads);

    //                KTOT NTILE SPLIT CMODE OUTH  LDA   LDB   LDC  MINCTA
    auto kQK = gemm<1024, 128, true,  1, false, 1024, 1024, 0,    2>;
    auto kV  = gemm<1024, 128, false, 3, false, 1024, 1024, 0,    2>;
    auto kS  = gemm<64,   128, true,  0, false, 64,   64,   1024, 2>;
    auto kPV = gemm<1024, 64,  false, 0, true,  1024, 1024, 64,   3>;
    auto kO  = gemm<1024, 128, false, 0, false, 1024, 1024, 1024, 2>;

    const int SM_SPLIT = 3 * 2 * 256 * 12 * 4;  // 73728 (3 stages, hi+lo)
    const int SM_P128  = 3 * 256 * 12 * 4;      // 36864
    const int SM_P64   = 3 * 192 * 12 * 4;      // 27648
    cudaFuncSetAttribute((const void*)kQK, cudaFuncAttributeMaxDynamicSharedMemorySize, SM_SPLIT);
    cudaFuncSetAttribute((const void*)kV,  cudaFuncAttributeMaxDynamicSharedMemorySize, SM_P128);
    cudaFuncSetAttribute((const void*)kS,  cudaFuncAttributeMaxDynamicSharedMemorySize, SM_SPLIT);
    cudaFuncSetAttribute((const void*)kPV, cudaFuncAttributeMaxDynamicSharedMemorySize, SM_P64);
    cudaFuncSetAttribute((const void*)kO,  cudaFuncAttributeMaxDynamicSharedMemorySize, SM_P128);

    // 1) prep
    prep_inputs<<<dim3(4096, 3), 256>>>(query, key_, value, qkh, qkl, v32);
    trans_qkv<<<dim3(32, 2, 48), 256>>>(q_w, k_w, v_w, qkwTh, qkwTl, vwT);
    trans_ow<<<dim3(32, 32), 256>>>(o_w, owT);

    // 2) Q+K projections (fp16x3) -> packed [b,h,i,s] hi/lo
    kQK<<<dim3(8, 64, 2), 256, SM_SPLIT>>>(qkh, qkl, qkwTh, qkwTl, wqkh, wqkl,
                                           8388608, 1048576, 8388608, 1.0f);

    // 3) V projection -> transposed packed [b,h,s,j]
    kV<<<dim3(8, 64, 1), 256, SM_P128>>>(v32, nullptr, vwT, nullptr, wvT, nullptr,
                                         0, 0, 0, 1.0f);

    // 4) scores = 0.25 * WQ WK^T per (b,h)  (fp16x3, fp32 out)
    kS<<<dim3(8, 8, 128), 256, SM_SPLIT>>>(wqkh, wqkl, wqkh + 8388608, wqkl + 8388608,
                                           sc, nullptr, 65536, 65536, 1048576, 0.25f);

    // 5) softmax over batch axis -> fp16 P
    softmax_b<<<16384, 256>>>(sc, P);

    // 6) heads = P @ WV per (b,h) -> packed [b,h,i,s] fp16
    kPV<<<dim3(1, 8, 128), 256, SM_P64>>>(P, nullptr, wvT, nullptr, hd, nullptr,
                                          1048576, 65536, 65536, 1.0f);

    // 7) out = heads_flat @ o_w -> fp32
    kO<<<dim3(8, 64, 1), 256, SM_P128>>>(hd, nullptr, owT, nullptr, out, nullptr,
                                         0, 0, 0, 1.0f);
}